// round 9
// baseline (speedup 1.0000x reference)
#include <cuda_runtime.h>
#include <cuda_bf16.h>
#include <cstdint>
#include <math.h>

#define SEQ  2048
#define EMB  2048
#define NH   16
#define HD   128

// ---------------- scratch (allocation-free: static device globals) ----------------
__device__ __nv_bfloat16 g_hsh[(size_t)SEQ * EMB];
__device__ __nv_bfloat16 g_hsl[(size_t)SEQ * EMB];
__device__ __nv_bfloat16 g_wqh[(size_t)EMB * EMB];
__device__ __nv_bfloat16 g_wql[(size_t)EMB * EMB];
__device__ __nv_bfloat16 g_wkh[(size_t)EMB * EMB];
__device__ __nv_bfloat16 g_wkl[(size_t)EMB * EMB];
__device__ __nv_bfloat16 g_wvh[(size_t)EMB * EMB];
__device__ __nv_bfloat16 g_wvl[(size_t)EMB * EMB];
__device__ __nv_bfloat16 g_woh[(size_t)EMB * EMB];
__device__ __nv_bfloat16 g_wol[(size_t)EMB * EMB];
__device__ __nv_bfloat16 g_qh[(size_t)SEQ * EMB];
__device__ __nv_bfloat16 g_ql[(size_t)SEQ * EMB];
__device__ __nv_bfloat16 g_kh[(size_t)SEQ * EMB];
__device__ __nv_bfloat16 g_kl[(size_t)SEQ * EMB];
__device__ __nv_bfloat16 g_vth[(size_t)EMB * SEQ];
__device__ __nv_bfloat16 g_vtl[(size_t)EMB * SEQ];
__device__ __nv_bfloat16 g_ctxh[(size_t)SEQ * EMB];
__device__ __nv_bfloat16 g_ctxl[(size_t)SEQ * EMB];

// ======================= helpers ==============
__device__ __forceinline__ uint32_t smem_u32(const void* p) {
    uint32_t a;
    asm("{ .reg .u64 t; cvta.to.shared.u64 t, %1; cvt.u32.u64 %0, t; }" : "=r"(a) : "l"(p));
    return a;
}
#define LDSM4(r0, r1, r2, r3, addr)                                               \
    asm volatile("ldmatrix.sync.aligned.m8n8.x4.shared.b16 {%0,%1,%2,%3}, [%4];"  \
        : "=r"(r0), "=r"(r1), "=r"(r2), "=r"(r3) : "r"(addr))
#define MMA_BF16(c, a, b0, b1)                                                    \
    asm volatile("mma.sync.aligned.m16n8k16.row.col.f32.bf16.bf16.f32 "           \
        "{%0,%1,%2,%3}, {%4,%5,%6,%7}, {%8,%9}, {%0,%1,%2,%3};"                   \
        : "+f"((c)[0]), "+f"((c)[1]), "+f"((c)[2]), "+f"((c)[3])                  \
        : "r"((a)[0]), "r"((a)[1]), "r"((a)[2]), "r"((a)[3]), "r"(b0), "r"(b1))
#define CP16(dst, src) \
    asm volatile("cp.async.cg.shared.global [%0], [%1], 16;" :: "r"(dst), "l"(src))
#define CP_COMMIT() asm volatile("cp.async.commit_group;")
#define CP_WAIT(n)  asm volatile("cp.async.wait_group %0;" :: "n"(n))

__device__ __forceinline__ void split_bf16(float x, __nv_bfloat16& h, __nv_bfloat16& l) {
    h = __float2bfloat16(x);
    l = __float2bfloat16(x - __bfloat162float(h));
}
__device__ __forceinline__ uint32_t pack_bf2(__nv_bfloat16 a, __nv_bfloat16 b) {
    __nv_bfloat162 p = __halves2bfloat162(a, b);
    return *(uint32_t*)&p;
}

// ---------------- input split: fp32 -> bf16 hi/lo ----------------
__global__ void __launch_bounds__(256) split_one(
    const float4* __restrict__ src, uint2* __restrict__ dh, uint2* __restrict__ dl)
{
    const int i = blockIdx.x * 256 + threadIdx.x;   // 1048576 float4s
    float4 x = src[i];
    __nv_bfloat16 h0, h1, h2, h3, l0, l1, l2, l3;
    split_bf16(x.x, h0, l0); split_bf16(x.y, h1, l1);
    split_bf16(x.z, h2, l2); split_bf16(x.w, h3, l3);
    dh[i] = make_uint2(pack_bf2(h0, h1), pack_bf2(h2, h3));
    dl[i] = make_uint2(pack_bf2(l0, l1), pack_bf2(l2, l3));
}

// ============ cp.async 4-stage HMMA NT GEMM + fused epilogue ============
// C = A @ B^T, A/B pre-split bf16 hi/lo. CTA 128x128, 16 warps 4x4 (warp 32x32).
// mode 0: RoPE+scale -> qh/ql   mode 1: RoPE -> kh/kl
// mode 2: transpose -> vth/vtl  mode 3: fp32 -> Cout
#define GKC   32
#define GNCH  (EMB / GKC)        // 64
#define GRS   40
#define GBUF  (128 * GRS)        // 5120 elems
#define GSTG  (4 * GBUF)         // Ah Al Bh Bl per stage
#define GSMEM (4 * GSTG * 2)     // 163840 B (>= 128*129*4 epilogue tile)

__global__ void __launch_bounds__(512, 1) gemm_cp(
    const __nv_bfloat16* __restrict__ Ah_, const __nv_bfloat16* __restrict__ Al_,
    const __nv_bfloat16* __restrict__ Bh0, const __nv_bfloat16* __restrict__ Bl0,
    const __nv_bfloat16* __restrict__ Bh1, const __nv_bfloat16* __restrict__ Bl1,
    const __nv_bfloat16* __restrict__ Bh2, const __nv_bfloat16* __restrict__ Bl2,
    __nv_bfloat16* __restrict__ Oh0, __nv_bfloat16* __restrict__ Ol0,
    __nv_bfloat16* __restrict__ Oh1, __nv_bfloat16* __restrict__ Ol1,
    __nv_bfloat16* __restrict__ Oh2, __nv_bfloat16* __restrict__ Ol2,
    float* __restrict__ Cout, int mode_base)
{
    const int mode = (mode_base >= 0) ? mode_base : (int)blockIdx.z;
    const __nv_bfloat16* Bh = (mode == 1) ? Bh1 : (mode == 2) ? Bh2 : Bh0;
    const __nv_bfloat16* Bl = (mode == 1) ? Bl1 : (mode == 2) ? Bl2 : Bl0;

    extern __shared__ __align__(16) __nv_bfloat16 sm[];
    const uint32_t su = smem_u32(sm);

    const int t    = threadIdx.x;
    const int lane = t & 31;
    const int wid  = t >> 5;
    const int wm   = wid & 3;
    const int wn   = wid >> 2;
    const int m0   = blockIdx.y * 128;
    const int n0   = blockIdx.x * 128;
    const int id   = lane >> 3;
    const int r8   = lane & 7;

    float acc[2][4][4];
#pragma unroll
    for (int i = 0; i < 2; i++)
#pragma unroll
        for (int j = 0; j < 4; j++)
#pragma unroll
            for (int c = 0; c < 4; c++) acc[i][j][c] = 0.0f;

    // ---- cp.async issue: one 64B row per thread (4 x 16B) ----
    const int mat  = t >> 7;       // 0:Ah 1:Al 2:Bh 3:Bl
    const int lrow = t & 127;
    const __nv_bfloat16* gsrc =
        (mat == 0) ? Ah_ + (size_t)(m0 + lrow) * EMB :
        (mat == 1) ? Al_ + (size_t)(m0 + lrow) * EMB :
        (mat == 2) ? Bh  + (size_t)(n0 + lrow) * EMB :
                     Bl  + (size_t)(n0 + lrow) * EMB;
    const uint32_t dbase = su + (uint32_t)(mat * GBUF + lrow * GRS) * 2;

    auto ISSUE = [&](int stage, int chunk) {
        const __nv_bfloat16* s = gsrc + chunk * GKC;
        const uint32_t d = dbase + (uint32_t)(stage * GSTG) * 2;
        CP16(d,      s);
        CP16(d + 16, s + 8);
        CP16(d + 32, s + 16);
        CP16(d + 48, s + 24);
    };
    auto COMPUTE = [&](int stage) {
        const uint32_t uAh = su + (uint32_t)(stage * GSTG) * 2;
        const uint32_t uAl = uAh + GBUF * 2;
        const uint32_t uBh = uAl + GBUF * 2;
        const uint32_t uBl = uBh + GBUF * 2;
#pragma unroll
        for (int kk = 0; kk < GKC; kk += 16) {
            uint32_t ah[2][4], al[2][4];
#pragma unroll
            for (int mt = 0; mt < 2; mt++) {
                const uint32_t offA =
                    ((wm * 32 + mt * 16 + (id & 1) * 8 + r8) * GRS + kk + (id >> 1) * 8) * 2;
                LDSM4(ah[mt][0], ah[mt][1], ah[mt][2], ah[mt][3], uAh + offA);
                LDSM4(al[mt][0], al[mt][1], al[mt][2], al[mt][3], uAl + offA);
            }
#pragma unroll
            for (int nt2 = 0; nt2 < 2; nt2++) {
                const uint32_t offB =
                    ((wn * 32 + nt2 * 16 + (id >> 1) * 8 + r8) * GRS + kk + (id & 1) * 8) * 2;
                uint32_t bh[4], bl[4];
                LDSM4(bh[0], bh[1], bh[2], bh[3], uBh + offB);
                LDSM4(bl[0], bl[1], bl[2], bl[3], uBl + offB);
#pragma unroll
                for (int mt = 0; mt < 2; mt++) {
                    MMA_BF16(acc[mt][nt2 * 2],     ah[mt], bh[0], bh[1]);
                    MMA_BF16(acc[mt][nt2 * 2],     ah[mt], bl[0], bl[1]);
                    MMA_BF16(acc[mt][nt2 * 2],     al[mt], bh[0], bh[1]);
                    MMA_BF16(acc[mt][nt2 * 2 + 1], ah[mt], bh[2], bh[3]);
                    MMA_BF16(acc[mt][nt2 * 2 + 1], ah[mt], bl[2], bl[3]);
                    MMA_BF16(acc[mt][nt2 * 2 + 1], al[mt], bh[2], bh[3]);
                }
            }
        }
    };

    // prologue: stages 0..2
#pragma unroll
    for (int s = 0; s < 3; s++) { ISSUE(s, s); CP_COMMIT(); }

    for (int chunk = 0; chunk < GNCH; chunk++) {
        CP_WAIT(2);
        __syncthreads();
        if (chunk + 3 < GNCH) { ISSUE((chunk + 3) & 3, chunk + 3); CP_COMMIT(); }
        COMPUTE(chunk & 3);
        __syncthreads();
    }
    CP_WAIT(0);
    __syncthreads();

    // ---- epilogue: acc -> fp32 smem tile (stride 129, conflict-free col reads) ----
    float* ct = (float*)sm;
#pragma unroll
    for (int mt = 0; mt < 2; mt++) {
        const int rl = wm * 32 + mt * 16 + (lane >> 2);
#pragma unroll
        for (int n = 0; n < 4; n++) {
            const int cl = wn * 32 + n * 8 + (lane & 3) * 2;
            ct[rl * 129 + cl]           = acc[mt][n][0];
            ct[rl * 129 + cl + 1]       = acc[mt][n][1];
            ct[(rl + 8) * 129 + cl]     = acc[mt][n][2];
            ct[(rl + 8) * 129 + cl + 1] = acc[mt][n][3];
        }
    }
    __syncthreads();

    const float SCALE = 0.08838834764831845f;
    if (mode <= 1) {
        __nv_bfloat16* Oh = mode ? Oh1 : Oh0;
        __nv_bfloat16* Ol = mode ? Ol1 : Ol0;
        for (int i = t; i < 128 * 64; i += 512) {
            const int r = i >> 6, d = i & 63;
            const float x0 = ct[r * 129 + d];
            const float x1 = ct[r * 129 + d + 64];
            const float inv_freq = powf(10000.0f, -(float)d * (1.0f / 64.0f));
            const float ang = (float)(m0 + r) * inv_freq;
            const float c = cosf(ang), sn = sinf(ang);
            float r0 = x0 * c - x1 * sn;
            float r1 = x1 * c + x0 * sn;
            if (mode == 0) { r0 *= SCALE; r1 *= SCALE; }
            __nv_bfloat16 h0, l0, h1, l1;
            split_bf16(r0, h0, l0); split_bf16(r1, h1, l1);
            const size_t o = (size_t)(m0 + r) * EMB + n0 + d;
            Oh[o] = h0;      Ol[o] = l0;
            Oh[o + 64] = h1; Ol[o + 64] = l1;
        }
    } else if (mode == 2) {
        for (int i = t; i < 128 * 128; i += 512) {
            const int sl = i & 127, el = i >> 7;
            const float x = ct[sl * 129 + el];
            __nv_bfloat16 h, l;
            split_bf16(x, h, l);
            const size_t o = (size_t)(n0 + el) * SEQ + m0 + sl;
            Oh2[o] = h; Ol2[o] = l;
        }
    } else {
        for (int i = t; i < 128 * 128; i += 512) {
            const int r = i >> 7, c = i & 127;
            Cout[(size_t)(m0 + r) * EMB + n0 + c] = ct[r * 129 + c];
        }
    }
}

// ---------------- flash attention (R7 8-warp config; epilogue -> bf16 splits) ----
#define QSTRIDE 136
#define KSTRIDE 136
#define VSTRIDE 72
#define PSTRIDE 72
#define QHo 0
#define QLo (128 * QSTRIDE)
#define KHo (2 * 128 * QSTRIDE)
#define KLo (KHo + 64 * KSTRIDE)
#define VHo (KHo + 2 * 64 * KSTRIDE)
#define VLo (VHo + 128 * VSTRIDE)
#define PHo (VHo + 2 * 128 * VSTRIDE)
#define PLo (PHo + 128 * PSTRIDE)
#define FB16_TOTAL (PHo + 2 * 128 * PSTRIDE)
#define FRED_OFF   (FB16_TOTAL * 2)
#define FSMEM_BYTES (FRED_OFF + 2 * 2 * 128 * 4)

__global__ void __launch_bounds__(256) flash_mma(
    const __nv_bfloat16* __restrict__ qh, const __nv_bfloat16* __restrict__ ql,
    const __nv_bfloat16* __restrict__ kh, const __nv_bfloat16* __restrict__ kl,
    const __nv_bfloat16* __restrict__ vth, const __nv_bfloat16* __restrict__ vtl,
    __nv_bfloat16* __restrict__ ctxh, __nv_bfloat16* __restrict__ ctxl)
{
    extern __shared__ __align__(16) __nv_bfloat16 fs[];
    float* pmax = (float*)((char*)fs + FRED_OFF);
    float* psum = pmax + 256;

    const int t    = threadIdx.x;
    const int lane = t & 31;
    const int wid  = t >> 5;
    const int wm   = wid & 3;
    const int wn   = wid >> 2;
    const int id   = lane >> 3;
    const int r8   = lane & 7;
    const int h    = blockIdx.y;
    const int m0   = blockIdx.x * 128;
    const int hb   = h * HD;

    const uint32_t uQH = smem_u32(fs + QHo);
    const uint32_t uQL = smem_u32(fs + QLo);
    const uint32_t uKH = smem_u32(fs + KHo);
    const uint32_t uKL = smem_u32(fs + KLo);
    const uint32_t uVH = smem_u32(fs + VHo);
    const uint32_t uVL = smem_u32(fs + VLo);
    const uint32_t uPH = smem_u32(fs + PHo);
    const uint32_t uPL = smem_u32(fs + PLo);

#pragma unroll
    for (int j = 0; j < 8; j++) {
        const int idx = j * 256 + t;
        const int r = idx >> 4;
        const int c = (idx & 15) * 8;
        *(uint4*)(fs + QHo + r * QSTRIDE + c) =
            *(const uint4*)(qh + (size_t)(m0 + r) * EMB + hb + c);
        *(uint4*)(fs + QLo + r * QSTRIDE + c) =
            *(const uint4*)(ql + (size_t)(m0 + r) * EMB + hb + c);
    }

    float acc_o[2][8][4];
#pragma unroll
    for (int i = 0; i < 2; i++)
#pragma unroll
        for (int j = 0; j < 8; j++)
#pragma unroll
            for (int c = 0; c < 4; c++) acc_o[i][j][c] = 0.0f;
    float m_r[2][2], l_r[2][2];
#pragma unroll
    for (int i = 0; i < 2; i++) { m_r[i][0] = m_r[i][1] = -1.0e30f; l_r[i][0] = l_r[i][1] = 0.0f; }

    for (int kb = 0; kb < SEQ / 64; kb++) {
        const int n0 = kb * 64;
        __syncthreads();

#pragma unroll
        for (int j = 0; j < 4; j++) {
            const int idx = j * 256 + t;
            {
                const int r = idx >> 4;
                const int c = (idx & 15) * 8;
                *(uint4*)(fs + KHo + r * KSTRIDE + c) =
                    *(const uint4*)(kh + (size_t)(n0 + r) * EMB + hb + c);
                *(uint4*)(fs + KLo + r * KSTRIDE + c) =
                    *(const uint4*)(kl + (size_t)(n0 + r) * EMB + hb + c);
            }
            {
                const int r = idx >> 3;
                const int c = (idx & 7) * 8;
                *(uint4*)(fs + VHo + r * VSTRIDE + c) =
                    *(const uint4*)(vth + (size_t)(hb + r) * SEQ + n0 + c);
                *(uint4*)(fs + VLo + r * VSTRIDE + c) =
                    *(const uint4*)(vtl + (size_t)(hb + r) * SEQ + n0 + c);
            }
        }
        __syncthreads();

        float acc_s[2][4][4];
#pragma unroll
        for (int i = 0; i < 2; i++)
#pragma unroll
            for (int j = 0; j < 4; j++)
#pragma unroll
                for (int c = 0; c < 4; c++) acc_s[i][j][c] = 0.0f;

#pragma unroll
        for (int kk = 0; kk < 128; kk += 16) {
            uint32_t ah[2][4], al[2][4];
#pragma unroll
            for (int mt = 0; mt < 2; mt++) {
                const uint32_t offA =
                    ((wm * 32 + mt * 16 + (id & 1) * 8 + r8) * QSTRIDE + kk + (id >> 1) * 8) * 2;
                LDSM4(ah[mt][0], ah[mt][1], ah[mt][2], ah[mt][3], uQH + offA);
                LDSM4(al[mt][0], al[mt][1], al[mt][2], al[mt][3], uQL + offA);
            }
#pragma unroll
            for (int nt2 = 0; nt2 < 2; nt2++) {
                const uint32_t offB =
                    ((wn * 32 + nt2 * 16 + (id >> 1) * 8 + r8) * KSTRIDE + kk + (id & 1) * 8) * 2;
                uint32_t bh[4], bl[4];
                LDSM4(bh[0], bh[1], bh[2], bh[3], uKH + offB);
                LDSM4(bl[0], bl[1], bl[2], bl[3], uKL + offB);
#pragma unroll
                for (int mt = 0; mt < 2; mt++) {
                    MMA_BF16(acc_s[mt][nt2 * 2],     ah[mt], bh[0], bh[1]);
                    MMA_BF16(acc_s[mt][nt2 * 2],     ah[mt], bl[0], bl[1]);
                    MMA_BF16(acc_s[mt][nt2 * 2],     al[mt], bh[0], bh[1]);
                    MMA_BF16(acc_s[mt][nt2 * 2 + 1], ah[mt], bh[2], bh[3]);
                    MMA_BF16(acc_s[mt][nt2 * 2 + 1], ah[mt], bl[2], bl[3]);
                    MMA_BF16(acc_s[mt][nt2 * 2 + 1], al[mt], bh[2], bh[3]);
                }
            }
        }

#pragma unroll
        for (int mt = 0; mt < 2; mt++)
#pragma unroll
            for (int hf = 0; hf < 2; hf++) {
                float mx = -1.0e30f;
#pragma unroll
                for (int nt = 0; nt < 4; nt++)
                    mx = fmaxf(mx, fmaxf(acc_s[mt][nt][hf * 2], acc_s[mt][nt][hf * 2 + 1]));
                mx = fmaxf(mx, __shfl_xor_sync(0xffffffffu, mx, 1));
                mx = fmaxf(mx, __shfl_xor_sync(0xffffffffu, mx, 2));
                const int row = wm * 32 + mt * 16 + hf * 8 + (lane >> 2);
                if ((lane & 3) == 0) pmax[wn * 128 + row] = mx;
            }
        __syncthreads();

        float corr_s[2][2];
#pragma unroll
        for (int mt = 0; mt < 2; mt++)
#pragma unroll
            for (int hf = 0; hf < 2; hf++) {
                const int row = wm * 32 + mt * 16 + hf * 8 + (lane >> 2);
                const float mb = fmaxf(pmax[row], pmax[128 + row]);
                const float mn = fmaxf(m_r[mt][hf], mb);
                const float corr = __expf(m_r[mt][hf] - mn);
                corr_s[mt][hf] = corr;
                m_r[mt][hf] = mn;
                float ps = 0.0f;
#pragma unroll
                for (int nt = 0; nt < 4; nt++) {
                    float p0 = __expf(acc_s[mt][nt][hf * 2]     - mn);
                    float p1 = __expf(acc_s[mt][nt][hf * 2 + 1] - mn);
                    ps += p0 + p1;
                    __nv_bfloat16 h0, l0, h1, l1;
                    split_bf16(p0, h0, l0); split_bf16(p1, h1, l1);
                    const int col = wn * 32 + nt * 8 + (lane & 3) * 2;
                    *(uint32_t*)(fs + PHo + row * PSTRIDE + col) = pack_bf2(h0, h1);
                    *(uint32_t*)(fs + PLo + row * PSTRIDE + col) = pack_bf2(l0, l1);
                }
                ps += __shfl_xor_sync(0xffffffffu, ps, 1);
                ps += __shfl_xor_sync(0xffffffffu, ps, 2);
                if ((lane & 3) == 0) psum[wn * 128 + row] = ps;
#pragma unroll
                for (int nt = 0; nt < 8; nt++) {
                    acc_o[mt][nt][hf * 2]     *= corr;
                    acc_o[mt][nt][hf * 2 + 1] *= corr;
                }
            }
        __syncthreads();

#pragma unroll
        for (int mt = 0; mt < 2; mt++)
#pragma unroll
            for (int hf = 0; hf < 2; hf++) {
                const int row = wm * 32 + mt * 16 + hf * 8 + (lane >> 2);
                l_r[mt][hf] = l_r[mt][hf] * corr_s[mt][hf] + psum[row] + psum[128 + row];
            }

#pragma unroll
        for (int kk = 0; kk < 64; kk += 16) {
            uint32_t pa[2][4], pl[2][4];
#pragma unroll
            for (int mt = 0; mt < 2; mt++) {
                const uint32_t offA =
                    ((wm * 32 + mt * 16 + (id & 1) * 8 + r8) * PSTRIDE + kk + (id >> 1) * 8) * 2;
                LDSM4(pa[mt][0], pa[mt][1], pa[mt][2], pa[mt][3], uPH + offA);
                LDSM4(pl[mt][0], pl[mt][1], pl[mt][2], pl[mt][3], uPL + offA);
            }
#pragma unroll
            for (int nt2 = 0; nt2 < 4; nt2++) {
                const uint32_t offB =
                    ((wn * 64 + nt2 * 16 + (id >> 1) * 8 + r8) * VSTRIDE + kk + (id & 1) * 8) * 2;
                uint32_t bh[4], bl[4];
                LDSM4(bh[0], bh[1], bh[2], bh[3], uVH + offB);
                LDSM4(bl[0], bl[1], bl[2], bl[3], uVL + offB);
#pragma unroll
                for (int mt = 0; mt < 2; mt++) {
                    MMA_BF16(acc_o[mt][nt2 * 2],     pa[mt], bh[0], bh[1]);
                    MMA_BF16(acc_o[mt][nt2 * 2],     pa[mt], bl[0], bl[1]);
                    MMA_BF16(acc_o[mt][nt2 * 2],     pl[mt], bh[0], bh[1]);
                    MMA_BF16(acc_o[mt][nt2 * 2 + 1], pa[mt], bh[2], bh[3]);
                    MMA_BF16(acc_o[mt][nt2 * 2 + 1], pa[mt], bl[2], bl[3]);
                    MMA_BF16(acc_o[mt][nt2 * 2 + 1], pl[mt], bh[2], bh[3]);
                }
            }
        }
    }

    // ---- epilogue: normalize, split to bf16 hi/lo, write ----
#pragma unroll
    for (int mt = 0; mt < 2; mt++)
#pragma unroll
        for (int hf = 0; hf < 2; hf++) {
            const float inv = 1.0f / l_r[mt][hf];
            const int row = m0 + wm * 32 + mt * 16 + hf * 8 + (lane >> 2);
#pragma unroll
            for (int nt = 0; nt < 8; nt++) {
                const int col = hb + wn * 64 + nt * 8 + (lane & 3) * 2;
                const float a0 = acc_o[mt][nt][hf * 2] * inv;
                const float a1 = acc_o[mt][nt][hf * 2 + 1] * inv;
                __nv_bfloat16 h0, l0, h1, l1;
                split_bf16(a0, h0, l0); split_bf16(a1, h1, l1);
                *(uint32_t*)(ctxh + (size_t)row * EMB + col) = pack_bf2(h0, h1);
                *(uint32_t*)(ctxl + (size_t)row * EMB + col) = pack_bf2(l0, l1);
            }
        }
}

// ---------------- launch ----------------
extern "C" void kernel_launch(void* const* d_in, const int* in_sizes, int n_in,
                              void* d_out, int out_size)
{
    const float* hs = (const float*)d_in[0];
    const float* Wq = (const float*)d_in[1];
    const float* Wk = (const float*)d_in[2];
    const float* Wv = (const float*)d_in[3];
    const float* Wo = (const float*)d_in[4];
    float* out = (float*)d_out;

    __nv_bfloat16 *hsh, *hsl, *wqh, *wql, *wkh, *wkl, *wvh, *wvl, *woh, *wol;
    __nv_bfloat16 *qh, *ql, *kh, *kl, *vth, *vtl, *ctxh, *ctxl;
    cudaGetSymbolAddress((void**)&hsh, g_hsh);   cudaGetSymbolAddress((void**)&hsl, g_hsl);
    cudaGetSymbolAddress((void**)&wqh, g_wqh);   cudaGetSymbolAddress((void**)&wql, g_wql);
    cudaGetSymbolAddress((void**)&wkh, g_wkh);   cudaGetSymbolAddress((void**)&wkl, g_wkl);
    cudaGetSymbolAddress((void**)&wvh, g_wvh);   cudaGetSymbolAddress((void**)&wvl, g_wvl);
    cudaGetSymbolAddress((void**)&woh, g_woh);   cudaGetSymbolAddress((void**)&wol, g_wol);
    cudaGetSymbolAddress((void**)&qh,  g_qh);    cudaGetSymbolAddress((void**)&ql,  g_ql);
    cudaGetSymbolAddress((void**)&kh,  g_kh);    cudaGetSymbolAddress((void**)&kl,  g_kl);
    cudaGetSymbolAddress((void**)&vth, g_vth);   cudaGetSymbolAddress((void**)&vtl, g_vtl);
    cudaGetSymbolAddress((void**)&ctxh, g_ctxh); cudaGetSymbolAddress((void**)&ctxl, g_ctxl);

    cudaFuncSetAttribute(gemm_cp,   cudaFuncAttributeMaxDynamicSharedMemorySize, GSMEM);
    cudaFuncSetAttribute(flash_mma, cudaFuncAttributeMaxDynamicSharedMemorySize, FSMEM_BYTES);

    // split fp32 inputs into bf16 hi/lo (each 2048x2048 -> 1M float4)
    split_one<<<4096, 256>>>((const float4*)hs, (uint2*)hsh, (uint2*)hsl);
    split_one<<<4096, 256>>>((const float4*)Wq, (uint2*)wqh, (uint2*)wql);
    split_one<<<4096, 256>>>((const float4*)Wk, (uint2*)wkh, (uint2*)wkl);
    split_one<<<4096, 256>>>((const float4*)Wv, (uint2*)wvh, (uint2*)wvl);
    split_one<<<4096, 256>>>((const float4*)Wo, (uint2*)woh, (uint2*)wol);

    // QKV projections, RoPE/scale/transpose fused into epilogue
    gemm_cp<<<dim3(EMB / 128, SEQ / 128, 3), 512, GSMEM>>>(
        hsh, hsl, wqh, wql, wkh, wkl, wvh, wvl,
        qh, ql, kh, kl, vth, vtl, out, -1);

    flash_mma<<<dim3(SEQ / 128, NH), 256, FSMEM_BYTES>>>(
        qh, ql, kh, kl, vth, vtl, ctxh, ctxl);

    // output projection (mode 3 -> fp32 out)
    gemm_cp<<<dim3(EMB / 128, SEQ / 128, 1), 512, GSMEM>>>(
        ctxh, ctxl, woh, wol, woh, wol, woh, wol,
        qh, ql, kh, kl, vth, vtl, out, 3);
}

// round 10
// speedup vs baseline: 1.3278x; 1.3278x over previous
#include <cuda_runtime.h>
#include <cuda_bf16.h>
#include <cstdint>
#include <math.h>

#define SEQ  2048
#define EMB  2048
#define NH   16
#define HD   128

// ---------------- scratch (allocation-free: static device globals) ----------------
__device__ float g_q[(size_t)SEQ * EMB];
__device__ float g_k[(size_t)SEQ * EMB];
__device__ float g_v[(size_t)SEQ * EMB];
__device__ float g_ctx[(size_t)SEQ * EMB];
__device__ __nv_bfloat16 g_qh[(size_t)SEQ * EMB];
__device__ __nv_bfloat16 g_ql[(size_t)SEQ * EMB];
__device__ __nv_bfloat16 g_kh[(size_t)SEQ * EMB];
__device__ __nv_bfloat16 g_kl[(size_t)SEQ * EMB];
__device__ __nv_bfloat16 g_vth[(size_t)EMB * SEQ];
__device__ __nv_bfloat16 g_vtl[(size_t)EMB * SEQ];

// ======================= helpers ==============
__device__ __forceinline__ uint32_t smem_u32(const void* p) {
    uint32_t a;
    asm("{ .reg .u64 t; cvta.to.shared.u64 t, %1; cvt.u32.u64 %0, t; }" : "=r"(a) : "l"(p));
    return a;
}
#define LDSM4(r0, r1, r2, r3, addr)                                               \
    asm volatile("ldmatrix.sync.aligned.m8n8.x4.shared.b16 {%0,%1,%2,%3}, [%4];"  \
        : "=r"(r0), "=r"(r1), "=r"(r2), "=r"(r3) : "r"(addr))
#define MMA_BF16(c, a, b0, b1)                                                    \
    asm volatile("mma.sync.aligned.m16n8k16.row.col.f32.bf16.bf16.f32 "           \
        "{%0,%1,%2,%3}, {%4,%5,%6,%7}, {%8,%9}, {%0,%1,%2,%3};"                   \
        : "+f"((c)[0]), "+f"((c)[1]), "+f"((c)[2]), "+f"((c)[3])                  \
        : "r"((a)[0]), "r"((a)[1]), "r"((a)[2]), "r"((a)[3]), "r"(b0), "r"(b1))
#define CP16(dst, src) \
    asm volatile("cp.async.cg.shared.global [%0], [%1], 16;" :: "r"(dst), "l"(src))
#define CP_COMMIT() asm volatile("cp.async.commit_group;")
#define CP_WAIT(n)  asm volatile("cp.async.wait_group %0;" :: "n"(n))

__device__ __forceinline__ void split_bf16(float x, __nv_bfloat16& h, __nv_bfloat16& l) {
    h = __float2bfloat16(x);
    l = __float2bfloat16(x - __bfloat162float(h));
}
__device__ __forceinline__ uint32_t pack_bf2(__nv_bfloat16 a, __nv_bfloat16 b) {
    __nv_bfloat162 p = __halves2bfloat162(a, b);
    return *(uint32_t*)&p;
}

// ============ HMMA NT GEMM (R8-proven): 512 threads, register-prefetch ============
#define KC      32
#define NCHUNK  (EMB / KC)
#define RSTRIDE 40
#define BUF_E   (128 * RSTRIDE)
#define STAGE_E (4 * BUF_E)
#define GSM_BYTES (2 * STAGE_E * 2)

__global__ void __launch_bounds__(512, 1) gemm_mma(
    const float* __restrict__ A,
    const float* __restrict__ B0, const float* __restrict__ B1, const float* __restrict__ B2,
    float* __restrict__ C0, float* __restrict__ C1, float* __restrict__ C2)
{
    const float* B = (blockIdx.z == 0) ? B0 : (blockIdx.z == 1) ? B1 : B2;
    float*       C = (blockIdx.z == 0) ? C0 : (blockIdx.z == 1) ? C1 : C2;

    extern __shared__ __align__(16) __nv_bfloat16 sm[];

    const int t    = threadIdx.x;
    const int lane = t & 31;
    const int wid  = t >> 5;
    const int wm   = wid & 3;
    const int wn   = wid >> 2;
    const int m0   = blockIdx.y * 128;
    const int n0   = blockIdx.x * 128;
    const int id   = lane >> 3;
    const int r8   = lane & 7;

    float acc[2][4][4];
#pragma unroll
    for (int i = 0; i < 2; i++)
#pragma unroll
        for (int j = 0; j < 4; j++)
#pragma unroll
            for (int c = 0; c < 4; c++) acc[i][j][c] = 0.0f;

    float4 pref[4];

    auto LOADG = [&](int k0) {
#pragma unroll
        for (int j = 0; j < 2; j++) {
            const int idx = j * 512 + t;
            const int row = idx >> 3;
            const int cg  = (idx & 7) << 2;
            pref[j]     = *(const float4*)(A + (size_t)(m0 + row) * EMB + k0 + cg);
            pref[2 + j] = *(const float4*)(B + (size_t)(n0 + row) * EMB + k0 + cg);
        }
    };
    auto STORES = [&](int s) {
        __nv_bfloat16* st = sm + s * STAGE_E;
#pragma unroll
        for (int mat = 0; mat < 2; mat++) {
            __nv_bfloat16* dh = st + (mat ? 2 * BUF_E : 0);
            __nv_bfloat16* dl = dh + BUF_E;
#pragma unroll
            for (int j = 0; j < 2; j++) {
                const int idx = j * 512 + t;
                const int row = idx >> 3;
                const int cg  = (idx & 7) << 2;
                float4 x = pref[mat * 2 + j];
                __nv_bfloat16 h0, h1, h2, h3, l0, l1, l2, l3;
                split_bf16(x.x, h0, l0); split_bf16(x.y, h1, l1);
                split_bf16(x.z, h2, l2); split_bf16(x.w, h3, l3);
                const int o = row * RSTRIDE + cg;
                *(uint2*)(dh + o) = make_uint2(pack_bf2(h0, h1), pack_bf2(h2, h3));
                *(uint2*)(dl + o) = make_uint2(pack_bf2(l0, l1), pack_bf2(l2, l3));
            }
        }
    };
    auto COMPUTE = [&](int s) {
        const uint32_t uAh = smem_u32(sm + s * STAGE_E);
        const uint32_t uAl = uAh + BUF_E * 2;
        const uint32_t uBh = uAl + BUF_E * 2;
        const uint32_t uBl = uBh + BUF_E * 2;
#pragma unroll
        for (int kk = 0; kk < KC; kk += 16) {
            uint32_t ah[2][4], al[2][4];
#pragma unroll
            for (int mt = 0; mt < 2; mt++) {
                const uint32_t offA =
                    ((wm * 32 + mt * 16 + (id & 1) * 8 + r8) * RSTRIDE + kk + (id >> 1) * 8) * 2;
                LDSM4(ah[mt][0], ah[mt][1], ah[mt][2], ah[mt][3], uAh + offA);
                LDSM4(al[mt][0], al[mt][1], al[mt][2], al[mt][3], uAl + offA);
            }
#pragma unroll
            for (int nt2 = 0; nt2 < 2; nt2++) {
                const uint32_t offB =
                    ((wn * 32 + nt2 * 16 + (id >> 1) * 8 + r8) * RSTRIDE + kk + (id & 1) * 8) * 2;
                uint32_t bh[4], bl[4];
                LDSM4(bh[0], bh[1], bh[2], bh[3], uBh + offB);
                LDSM4(bl[0], bl[1], bl[2], bl[3], uBl + offB);
#pragma unroll
                for (int mt = 0; mt < 2; mt++) {
                    MMA_BF16(acc[mt][nt2 * 2],     ah[mt], bh[0], bh[1]);
                    MMA_BF16(acc[mt][nt2 * 2],     ah[mt], bl[0], bl[1]);
                    MMA_BF16(acc[mt][nt2 * 2],     al[mt], bh[0], bh[1]);
                    MMA_BF16(acc[mt][nt2 * 2 + 1], ah[mt], bh[2], bh[3]);
                    MMA_BF16(acc[mt][nt2 * 2 + 1], ah[mt], bl[2], bl[3]);
                    MMA_BF16(acc[mt][nt2 * 2 + 1], al[mt], bh[2], bh[3]);
                }
            }
        }
    };

    LOADG(0);
    STORES(0);
    __syncthreads();

    for (int chunk = 0; chunk < NCHUNK; chunk++) {
        if (chunk + 1 < NCHUNK) LOADG((chunk + 1) * KC);
        COMPUTE(chunk & 1);
        if (chunk + 1 < NCHUNK) STORES((chunk + 1) & 1);
        __syncthreads();
    }

#pragma unroll
    for (int mt = 0; mt < 2; mt++) {
        const int row = m0 + wm * 32 + mt * 16 + (lane >> 2);
#pragma unroll
        for (int n = 0; n < 4; n++) {
            const int col = n0 + wn * 32 + n * 8 + (lane & 3) * 2;
            *(float2*)(C + (size_t)row * EMB + col) =
                make_float2(acc[mt][n][0], acc[mt][n][1]);
            *(float2*)(C + (size_t)(row + 8) * EMB + col) =
                make_float2(acc[mt][n][2], acc[mt][n][3]);
        }
    }
}

// ---------- RoPE + scale + split-convert ----------
__global__ void __launch_bounds__(64) rope_convert(
    const float* __restrict__ q, const float* __restrict__ k,
    __nv_bfloat16* __restrict__ qh, __nv_bfloat16* __restrict__ ql,
    __nv_bfloat16* __restrict__ kh, __nv_bfloat16* __restrict__ kl)
{
    const int s = blockIdx.x;
    const int h = blockIdx.y;
    const int i = threadIdx.x;
    const float SCALE = 0.08838834764831845f;

    const float inv_freq = powf(10000.0f, -(float)i * (1.0f / 64.0f));
    const float ang = (float)s * inv_freq;
    const float c  = cosf(ang);
    const float sn = sinf(ang);

    const size_t base = (size_t)s * EMB + (size_t)h * HD;

    {
        float x0 = q[base + i], x1 = q[base + i + 64];
        float r0 = (x0 * c - x1 * sn) * SCALE;
        float r1 = (x1 * c + x0 * sn) * SCALE;
        __nv_bfloat16 h0, l0, h1, l1;
        split_bf16(r0, h0, l0); split_bf16(r1, h1, l1);
        qh[base + i] = h0;      ql[base + i] = l0;
        qh[base + i + 64] = h1; ql[base + i + 64] = l1;
    }
    {
        float x0 = k[base + i], x1 = k[base + i + 64];
        float r0 = x0 * c - x1 * sn;
        float r1 = x1 * c + x0 * sn;
        __nv_bfloat16 h0, l0, h1, l1;
        split_bf16(r0, h0, l0); split_bf16(r1, h1, l1);
        kh[base + i] = h0;      kl[base + i] = l0;
        kh[base + i + 64] = h1; kl[base + i + 64] = l1;
    }
}

// ---------- V transpose + split ----------
__global__ void __launch_bounds__(256) vtrans(
    const float* __restrict__ v,
    __nv_bfloat16* __restrict__ vth, __nv_bfloat16* __restrict__ vtl)
{
    __shared__ float tile[32][33];
    const int s0 = blockIdx.x * 32;
    const int e0 = blockIdx.y * 32;
    const int tx = threadIdx.x & 31;
    const int ty = threadIdx.x >> 5;

#pragma unroll
    for (int j = 0; j < 4; j++) {
        const int r = ty + j * 8;
        tile[r][tx] = v[(size_t)(s0 + r) * EMB + e0 + tx];
    }
    __syncthreads();
#pragma unroll
    for (int j = 0; j < 4; j++) {
        const int el = ty + j * 8;
        const float x = tile[tx][el];
        __nv_bfloat16 h, l;
        split_bf16(x, h, l);
        const size_t o = (size_t)(e0 + el) * SEQ + s0 + tx;
        vth[o] = h;
        vtl[o] = l;
    }
}

// ---------------- flash attention: register-resident P (FA2 layout) ------------
// 256 threads, 8 warps; warp w owns S rows w*16..w*16+15 x ALL 64 kv cols.
// Softmax warp-local; S-accumulator fragments reused directly as PV A-fragments.
// K/V double-buffered via cp.async.
#define QSTRIDE 136
#define KSTRIDE 136
#define VSTRIDE 72
#define FQH 0
#define FQL (128 * QSTRIDE)                  // 17408
#define FKV0 (2 * 128 * QSTRIDE)             // 34816
#define KVSTG (2 * 64 * KSTRIDE + 2 * 128 * VSTRIDE)   // 35840
#define KH_OFF 0
#define KL_OFF (64 * KSTRIDE)                // 8704
#define VH_OFF (2 * 64 * KSTRIDE)            // 17408
#define VL_OFF (VH_OFF + 128 * VSTRIDE)      // 26624
#define FSMEM_BYTES ((FKV0 + 2 * KVSTG) * 2) // 212992

__global__ void __launch_bounds__(256, 1) flash_reg(
    const __nv_bfloat16* __restrict__ qh, const __nv_bfloat16* __restrict__ ql,
    const __nv_bfloat16* __restrict__ kh, const __nv_bfloat16* __restrict__ kl,
    const __nv_bfloat16* __restrict__ vth, const __nv_bfloat16* __restrict__ vtl,
    float* __restrict__ ctx)
{
    extern __shared__ __align__(16) __nv_bfloat16 fs[];
    const uint32_t su = smem_u32(fs);

    const int t    = threadIdx.x;
    const int lane = t & 31;
    const int wid  = t >> 5;           // 0..7: 16-row band
    const int id   = lane >> 3;
    const int r8   = lane & 7;
    const int h    = blockIdx.y;
    const int m0   = blockIdx.x * 128;
    const int hb   = h * HD;

    // ---- load Q tile (hi/lo) ----
#pragma unroll
    for (int j = 0; j < 8; j++) {
        const int idx = j * 256 + t;
        const int r = idx >> 4;
        const int c = (idx & 15) * 8;
        *(uint4*)(fs + FQH + r * QSTRIDE + c) =
            *(const uint4*)(qh + (size_t)(m0 + r) * EMB + hb + c);
        *(uint4*)(fs + FQL + r * QSTRIDE + c) =
            *(const uint4*)(ql + (size_t)(m0 + r) * EMB + hb + c);
    }

    // ---- cp.async K/V stage issue ----
    auto ISSUE_KV = [&](int stage, int n0) {
        const uint32_t sb = su + (uint32_t)(FKV0 + stage * KVSTG) * 2;
#pragma unroll
        for (int j = 0; j < 8; j++) {       // K: 2048 16B chunks
            const int c = j * 256 + t;
            const int buf = c >> 10;
            const int cc = c & 1023;
            const int row = cc >> 4;
            const int col = (cc & 15) * 8;
            const __nv_bfloat16* src =
                (buf ? kl : kh) + (size_t)(n0 + row) * EMB + hb + col;
            CP16(sb + (uint32_t)(buf ? KL_OFF : KH_OFF) * 2 +
                 (uint32_t)(row * KSTRIDE + col) * 2, src);
        }
#pragma unroll
        for (int j = 0; j < 8; j++) {       // V: 2048 16B chunks
            const int c = j * 256 + t;
            const int buf = c >> 10;
            const int cc = c & 1023;
            const int row = cc >> 3;
            const int col = (cc & 7) * 8;
            const __nv_bfloat16* src =
                (buf ? vtl : vth) + (size_t)(hb + row) * SEQ + n0 + col;
            CP16(sb + (uint32_t)(buf ? VL_OFF : VH_OFF) * 2 +
                 (uint32_t)(row * VSTRIDE + col) * 2, src);
        }
        CP_COMMIT();
    };

    float acc_o[16][4];
#pragma unroll
    for (int j = 0; j < 16; j++)
#pragma unroll
        for (int c = 0; c < 4; c++) acc_o[j][c] = 0.0f;
    float m_r[2] = {-1.0e30f, -1.0e30f};
    float l_r[2] = {0.0f, 0.0f};

    ISSUE_KV(0, 0);

    for (int kb = 0; kb < SEQ / 64; kb++) {
        if (kb + 1 < SEQ / 64) { ISSUE_KV((kb + 1) & 1, (kb + 1) * 64); CP_WAIT(1); }
        else                   { CP_WAIT(0); }
        __syncthreads();

        const uint32_t sb = su + (uint32_t)(FKV0 + (kb & 1) * KVSTG) * 2;
        const uint32_t uKH = sb + (uint32_t)KH_OFF * 2;
        const uint32_t uKL = sb + (uint32_t)KL_OFF * 2;
        const uint32_t uVH = sb + (uint32_t)VH_OFF * 2;
        const uint32_t uVL = sb + (uint32_t)VL_OFF * 2;

        // ---- S = Q @ K^T: warp tile 16 x 64 (3-term) ----
        float acc_s[8][4];
#pragma unroll
        for (int j = 0; j < 8; j++)
#pragma unroll
            for (int c = 0; c < 4; c++) acc_s[j][c] = 0.0f;

#pragma unroll
        for (int kk = 0; kk < 128; kk += 16) {
            const uint32_t offA =
                ((wid * 16 + (id & 1) * 8 + r8) * QSTRIDE + kk + (id >> 1) * 8) * 2;
            uint32_t ah[4], al[4];
            LDSM4(ah[0], ah[1], ah[2], ah[3], su + FQH * 2 + offA);
            LDSM4(al[0], al[1], al[2], al[3], su + FQL * 2 + offA);
#pragma unroll
            for (int nt2 = 0; nt2 < 4; nt2++) {
                const uint32_t offB =
                    ((nt2 * 16 + (id >> 1) * 8 + r8) * KSTRIDE + kk + (id & 1) * 8) * 2;
                uint32_t bh[4], bl[4];
                LDSM4(bh[0], bh[1], bh[2], bh[3], uKH + offB);
                LDSM4(bl[0], bl[1], bl[2], bl[3], uKL + offB);
                MMA_BF16(acc_s[nt2 * 2],     ah, bh[0], bh[1]);
                MMA_BF16(acc_s[nt2 * 2],     ah, bl[0], bl[1]);
                MMA_BF16(acc_s[nt2 * 2],     al, bh[0], bh[1]);
                MMA_BF16(acc_s[nt2 * 2 + 1], ah, bh[2], bh[3]);
                MMA_BF16(acc_s[nt2 * 2 + 1], ah, bl[2], bl[3]);
                MMA_BF16(acc_s[nt2 * 2 + 1], al, bh[2], bh[3]);
            }
        }

        // ---- warp-local online softmax; exp in place ----
#pragma unroll
        for (int hf = 0; hf < 2; hf++) {
            float mx = -1.0e30f;
#pragma unroll
            for (int nt = 0; nt < 8; nt++)
                mx = fmaxf(mx, fmaxf(acc_s[nt][hf * 2], acc_s[nt][hf * 2 + 1]));
            mx = fmaxf(mx, __shfl_xor_sync(0xffffffffu, mx, 1));
            mx = fmaxf(mx, __shfl_xor_sync(0xffffffffu, mx, 2));
            const float mn = fmaxf(m_r[hf], mx);
            const float corr = __expf(m_r[hf] - mn);
            m_r[hf] = mn;
            float ps = 0.0f;
#pragma unroll
            for (int nt = 0; nt < 8; nt++) {
                float p0 = __expf(acc_s[nt][hf * 2]     - mn);
                float p1 = __expf(acc_s[nt][hf * 2 + 1] - mn);
                acc_s[nt][hf * 2]     = p0;
                acc_s[nt][hf * 2 + 1] = p1;
                ps += p0 + p1;
            }
            ps += __shfl_xor_sync(0xffffffffu, ps, 1);
            ps += __shfl_xor_sync(0xffffffffu, ps, 2);
            l_r[hf] = l_r[hf] * corr + ps;
#pragma unroll
            for (int nt = 0; nt < 16; nt++) {
                acc_o[nt][hf * 2]     *= corr;
                acc_o[nt][hf * 2 + 1] *= corr;
            }
        }

        // ---- pack P (C-fragment == A-fragment identity), split hi/lo ----
        uint32_t pa[4][4], pl[4][4];
#pragma unroll
        for (int k2 = 0; k2 < 4; k2++) {
#pragma unroll
            for (int half = 0; half < 2; half++) {   // tiles 2k2, 2k2+1
                const int nt = k2 * 2 + half;
#pragma unroll
                for (int rr = 0; rr < 2; rr++) {      // c01 (row), c23 (row+8)
                    __nv_bfloat16 h0, l0, h1, l1;
                    split_bf16(acc_s[nt][rr * 2],     h0, l0);
                    split_bf16(acc_s[nt][rr * 2 + 1], h1, l1);
                    pa[k2][half * 2 + rr] = pack_bf2(h0, h1);
                    pl[k2][half * 2 + rr] = pack_bf2(l0, l1);
                }
            }
        }

        // ---- O += P @ V: warp tile 16 x 128 (3-term), A from registers ----
#pragma unroll
        for (int k2 = 0; k2 < 4; k2++) {
#pragma unroll
            for (int nt2 = 0; nt2 < 8; nt2++) {
                const uint32_t offB =
                    ((nt2 * 16 + (id >> 1) * 8 + r8) * VSTRIDE + k2 * 16 + (id & 1) * 8) * 2;
                uint32_t bh[4], bl[4];
                LDSM4(bh[0], bh[1], bh[2], bh[3], uVH + offB);
                LDSM4(bl[0], bl[1], bl[2], bl[3], uVL + offB);
                MMA_BF16(acc_o[nt2 * 2],     pa[k2], bh[0], bh[1]);
                MMA_BF16(acc_o[nt2 * 2],     pa[k2], bl[0], bl[1]);
                MMA_BF16(acc_o[nt2 * 2],     pl[k2], bh[0], bh[1]);
                MMA_BF16(acc_o[nt2 * 2 + 1], pa[k2], bh[2], bh[3]);
                MMA_BF16(acc_o[nt2 * 2 + 1], pa[k2], bl[2], bl[3]);
                MMA_BF16(acc_o[nt2 * 2 + 1], pl[k2], bh[2], bh[3]);
            }
        }
        __syncthreads();   // all warps done with this stage before reuse
    }

    // ---- epilogue: normalize, write fp32 ctx ----
#pragma unroll
    for (int hf = 0; hf < 2; hf++) {
        const float inv = 1.0f / l_r[hf];
        const int row = m0 + wid * 16 + hf * 8 + (lane >> 2);
#pragma unroll
        for (int nt = 0; nt < 16; nt++) {
            const int col = hb + nt * 8 + (lane & 3) * 2;
            *(float2*)(ctx + (size_t)row * EMB + col) =
                make_float2(acc_o[nt][hf * 2] * inv, acc_o[nt][hf * 2 + 1] * inv);
        }
    }
}

// ---------------- launch ----------------
extern "C" void kernel_launch(void* const* d_in, const int* in_sizes, int n_in,
                              void* d_out, int out_size)
{
    const float* hs = (const float*)d_in[0];
    const float* Wq = (const float*)d_in[1];
    const float* Wk = (const float*)d_in[2];
    const float* Wv = (const float*)d_in[3];
    const float* Wo = (const float*)d_in[4];
    float* out = (float*)d_out;

    float *q, *k, *v, *ctx;
    __nv_bfloat16 *qh, *ql, *kh, *kl, *vth, *vtl;
    cudaGetSymbolAddress((void**)&q,   g_q);
    cudaGetSymbolAddress((void**)&k,   g_k);
    cudaGetSymbolAddress((void**)&v,   g_v);
    cudaGetSymbolAddress((void**)&ctx, g_ctx);
    cudaGetSymbolAddress((void**)&qh,  g_qh);
    cudaGetSymbolAddress((void**)&ql,  g_ql);
    cudaGetSymbolAddress((void**)&kh,  g_kh);
    cudaGetSymbolAddress((void**)&kl,  g_kl);
    cudaGetSymbolAddress((void**)&vth, g_vth);
    cudaGetSymbolAddress((void**)&vtl, g_vtl);

    cudaFuncSetAttribute(gemm_mma,  cudaFuncAttributeMaxDynamicSharedMemorySize, GSM_BYTES);
    cudaFuncSetAttribute(flash_reg, cudaFuncAttributeMaxDynamicSharedMemorySize, FSMEM_BYTES);

    gemm_mma<<<dim3(EMB / 128, SEQ / 128, 3), 512, GSM_BYTES>>>(hs, Wq, Wk, Wv, q, k, v);

    rope_convert<<<dim3(SEQ, NH), 64>>>(q, k, qh, ql, kh, kl);
    vtrans<<<dim3(SEQ / 32, EMB / 32), 256>>>(v, vth, vtl);

    flash_reg<<<dim3(SEQ / 128, NH), 256, FSMEM_BYTES>>>(qh, ql, kh, kl, vth, vtl, ctx);

    gemm_mma<<<dim3(EMB / 128, SEQ / 128, 1), 512, GSM_BYTES>>>(ctx, Wo, Wo, Wo, out, out, out);
}